// round 3
// baseline (speedup 1.0000x reference)
#include <cuda_runtime.h>
#include <cstdint>

// Problem dims
#define B_   32
#define T_   128
#define D_   2
#define E_   64
#define L_   64
#define H_   256
#define P_   128
#define IN_  130       // E + L + D
#define BP_  4096      // B*P
#define G3H_ 768       // 3*H

#define SPB_      0.5413248538970947f
#define HALF_L2PI 0.9189385332046727f
#define LOGP_     4.852030263919617f   // log(128)

// ---------------- persistent device state ----------------
__device__ float g_z[BP_ * L_];        // carry z (resampled)
__device__ float g_znew[BP_ * L_];     // z_new before resample
__device__ float g_h[BP_ * H_];        // GRU hidden
__device__ float g_la[BP_];            // log_alpha
__device__ float g_lw[BP_];            // log_w
__device__ float g_lp[B_];             // log_p accumulator
__device__ float g_embed[B_ * T_ * E_];
__device__ float g_WihT[IN_ * G3H_];   // [k][j]
__device__ float g_WhhT[H_ * G3H_];    // [k][j]
__device__ unsigned g_keys[T_ * 4];    // per-step {samp0,samp1,res0,res1}

// ---------------- threefry-2x32 (matches JAX exactly) ----------------
__device__ __forceinline__ void tf2x32(unsigned k0, unsigned k1,
                                       unsigned x0, unsigned x1,
                                       unsigned& o0, unsigned& o1) {
    unsigned ks2 = k0 ^ k1 ^ 0x1BD11BDAu;
    x0 += k0; x1 += k1;
#define TF_RND(r) { x0 += x1; x1 = (x1 << (r)) | (x1 >> (32 - (r))); x1 ^= x0; }
    TF_RND(13) TF_RND(15) TF_RND(26) TF_RND(6)   x0 += k1;  x1 += ks2 + 1u;
    TF_RND(17) TF_RND(29) TF_RND(16) TF_RND(24)  x0 += ks2; x1 += k0 + 2u;
    TF_RND(13) TF_RND(15) TF_RND(26) TF_RND(6)   x0 += k0;  x1 += k1 + 3u;
    TF_RND(17) TF_RND(29) TF_RND(16) TF_RND(24)  x0 += k1;  x1 += ks2 + 4u;
    TF_RND(13) TF_RND(15) TF_RND(26) TF_RND(6)   x0 += ks2; x1 += k0 + 5u;
#undef TF_RND
    o0 = x0; o1 = x1;
}

// partitionable random_bits for 32-bit: counter = (0, i), output out0^out1
__device__ __forceinline__ unsigned rbits32(unsigned k0, unsigned k1, unsigned i) {
    unsigned o0, o1;
    tf2x32(k0, k1, 0u, i, o0, o1);
    return o0 ^ o1;
}

// bits -> [0,1) float exactly as JAX: (bits>>9 | 0x3f800000) - 1
__device__ __forceinline__ float bits_to_u01(unsigned bits) {
    return __uint_as_float((bits >> 9) | 0x3f800000u) - 1.0f;
}

// XLA ErfInv (float32, Giles polynomial) — matches lax.erf_inv lowering
__device__ __forceinline__ float erfinv_x(float x) {
    float w = -log1pf(-x * x);
    float p;
    if (w < 5.0f) {
        w -= 2.5f;
        p = 2.81022636e-08f;
        p = fmaf(p, w, 3.43273939e-07f);
        p = fmaf(p, w, -3.5233877e-06f);
        p = fmaf(p, w, -4.39150654e-06f);
        p = fmaf(p, w, 0.00021858087f);
        p = fmaf(p, w, -0.00125372503f);
        p = fmaf(p, w, -0.00417768164f);
        p = fmaf(p, w, 0.246640727f);
        p = fmaf(p, w, 1.50140941f);
    } else {
        w = sqrtf(w) - 3.0f;
        p = -0.000200214257f;
        p = fmaf(p, w, 0.000100950558f);
        p = fmaf(p, w, 0.00134934322f);
        p = fmaf(p, w, -0.00367342844f);
        p = fmaf(p, w, 0.00573950773f);
        p = fmaf(p, w, -0.0076224613f);
        p = fmaf(p, w, 0.00943887047f);
        p = fmaf(p, w, 1.00167406f);
        p = fmaf(p, w, 2.83297682f);
    }
    return p * x;
}

// standard normal draw at flat index i under key (k0,k1)  (jax.random.normal)
__device__ __forceinline__ float normal_draw(unsigned k0, unsigned k1, unsigned i) {
    float f = bits_to_u01(rbits32(k0, k1, i));
    const float lo = -0.99999994039535522f;          // nextafter(-1,0)
    float u = fmaxf(lo, fmaf(f, 2.0f, lo));          // (hi-lo) rounds to 2.0f in f32
    return 1.41421356f * erfinv_x(u);                // sqrt(2) as f32
}

// gumbel draw at flat index i (jax.random.gumbel)
__device__ __forceinline__ float gumbel_draw(unsigned k0, unsigned k1, unsigned i) {
    float f = bits_to_u01(rbits32(k0, k1, i));
    const float tiny = 1.17549435e-38f;
    float u = fmaxf(tiny, f + tiny);                 // f*(1-tiny)+tiny, (1-tiny)->1.0f
    return -logf(-logf(u));
}

__device__ __forceinline__ float softplus_j(float x) {  // jnp.logaddexp(x, 0)
    return fmaxf(x, 0.0f) + log1pf(expf(-fabsf(x)));
}

__device__ __forceinline__ float nlp(float x, float mu, float sig) {
    float t = (x - mu) / sig;
    return fmaf(-0.5f * t, t, -logf(sig) - HALF_L2PI);
}

// ---------------- setup: zero state, transpose W_ih/W_hh, embed ----------------
__global__ void k_setup(const float* __restrict__ x, const float* __restrict__ W_emb,
                        const float* __restrict__ b_emb, const float* __restrict__ W_ih,
                        const float* __restrict__ W_hh) {
    const int N_H = BP_ * H_, N_Z = BP_ * L_, N_LW = BP_, N_LP = B_;
    const int N_IH = G3H_ * IN_, N_HH = G3H_ * H_, N_EMB = B_ * T_ * E_;
    const int total = N_H + N_Z + N_LW + N_LP + N_IH + N_HH + N_EMB;
    int stride = gridDim.x * blockDim.x;
    for (int i = blockIdx.x * blockDim.x + threadIdx.x; i < total; i += stride) {
        int r = i;
        if (r < N_H)  { g_h[r] = 0.0f; continue; }  r -= N_H;
        if (r < N_Z)  { g_z[r] = 0.0f; continue; }  r -= N_Z;
        if (r < N_LW) { g_lw[r] = 0.0f; continue; } r -= N_LW;
        if (r < N_LP) { g_lp[r] = 0.0f; continue; } r -= N_LP;
        if (r < N_IH) { int j = r / IN_, k = r % IN_; g_WihT[k * G3H_ + j] = W_ih[r]; continue; } r -= N_IH;
        if (r < N_HH) { int j = r >> 8, k = r & 255; g_WhhT[k * G3H_ + j] = W_hh[r]; continue; }  r -= N_HH;
        { int bt = r >> 6, e = r & 63;
          g_embed[r] = fmaf(x[bt * 2], W_emb[e], x[bt * 2 + 1] * W_emb[E_ + e]) + b_emb[e]; }
    }
}

// ---------------- key chain: fold-like split, key = (0,42) ----------------
__global__ void k_keys() {
    if (threadIdx.x == 0 && blockIdx.x == 0) {
        unsigned k0 = 0u, k1 = 42u;
        for (int t = 0; t < T_; ++t) {
            unsigned n0, n1, s0, s1, r0, r1;
            tf2x32(k0, k1, 0u, 0u, n0, n1);   // keys[0] -> carry
            tf2x32(k0, k1, 0u, 1u, s0, s1);   // keys[1] -> k_samp
            tf2x32(k0, k1, 0u, 2u, r0, r1);   // keys[2] -> k_res
            g_keys[t * 4 + 0] = s0; g_keys[t * 4 + 1] = s1;
            g_keys[t * 4 + 2] = r0; g_keys[t * 4 + 3] = r1;
            k0 = n0; k1 = n1;
        }
    }
}

// ---------------- per-step particle kernel: 16 particles / block ----------------
__global__ void __launch_bounds__(256, 1)
k_particle(const float* __restrict__ y,
           const float* __restrict__ b_ih, const float* __restrict__ b_hh,
           const float* __restrict__ W_enc, const float* __restrict__ b_enc,
           const float* __restrict__ W_pr,  const float* __restrict__ b_pr,
           const float* __restrict__ W_dec, const float* __restrict__ b_dec,
           int t) {
    __shared__ float s_inp[16 * IN_];   // [p][130]
    __shared__ float s_h[16 * H_];      // [p][256]  (h_old, overwritten in-place with h_new)
    __shared__ float s_enc[16 * 128];   // [p][128]
    __shared__ float s_pr[16 * 128];    // [p][128]
    __shared__ float s_znew[16 * L_];   // [p][64]

    const int bid = blockIdx.x;
    const int b = bid >> 3;
    const int pbase = (bid & 7) << 4;
    const int tid = threadIdx.x;

    // ---- load inputs ----
    for (int i = tid; i < 16 * IN_; i += 256) {
        int p = i / IN_, k = i - p * IN_;
        float v;
        if (k < E_)            v = g_embed[(b * T_ + t) * E_ + k];
        else if (k < E_ + L_)  v = g_z[(b * P_ + pbase + p) * L_ + (k - E_)];
        else                   v = y[(b * T_ + t) * D_ + (k - E_ - L_)];
        s_inp[p * IN_ + k] = v;
    }
    for (int i = tid; i < 16 * H_; i += 256) {
        int p = i >> 8, k = i & 255;
        s_h[p * H_ + k] = g_h[(b * P_ + pbase + p) * H_ + k];
    }
    __syncthreads();

    // ---- gi = inp @ W_ih^T + b_ih ;  gh = h @ W_hh^T + b_hh ----
    float aI0[16], aI1[16], aI2[16], aH0[16], aH1[16], aH2[16];
    {
        float bi0 = b_ih[tid], bi1 = b_ih[tid + 256], bi2 = b_ih[tid + 512];
        float bh0 = b_hh[tid], bh1 = b_hh[tid + 256], bh2 = b_hh[tid + 512];
#pragma unroll
        for (int p = 0; p < 16; ++p) {
            aI0[p] = bi0; aI1[p] = bi1; aI2[p] = bi2;
            aH0[p] = bh0; aH1[p] = bh1; aH2[p] = bh2;
        }
    }
#pragma unroll 2
    for (int k = 0; k < IN_; ++k) {
        float w0 = g_WihT[k * G3H_ + tid];
        float w1 = g_WihT[k * G3H_ + tid + 256];
        float w2 = g_WihT[k * G3H_ + tid + 512];
#pragma unroll
        for (int p = 0; p < 16; ++p) {
            float xv = s_inp[p * IN_ + k];
            aI0[p] = fmaf(w0, xv, aI0[p]);
            aI1[p] = fmaf(w1, xv, aI1[p]);
            aI2[p] = fmaf(w2, xv, aI2[p]);
        }
    }
#pragma unroll 2
    for (int k = 0; k < H_; ++k) {
        float w0 = g_WhhT[k * G3H_ + tid];
        float w1 = g_WhhT[k * G3H_ + tid + 256];
        float w2 = g_WhhT[k * G3H_ + tid + 512];
#pragma unroll
        for (int p = 0; p < 16; ++p) {
            float hv = s_h[p * H_ + k];
            aH0[p] = fmaf(w0, hv, aH0[p]);
            aH1[p] = fmaf(w1, hv, aH1[p]);
            aH2[p] = fmaf(w2, hv, aH2[p]);
        }
    }
    __syncthreads();   // all reads of s_h complete before in-place overwrite

    // ---- GRU gates (thread owns j = tid of all three gate blocks) ----
#pragma unroll
    for (int p = 0; p < 16; ++p) {
        float r = 1.0f / (1.0f + expf(-(aI0[p] + aH0[p])));
        float u = 1.0f / (1.0f + expf(-(aI1[p] + aH1[p])));
        float n = tanhf(fmaf(r, aH2[p], aI2[p]));
        float hold = s_h[p * H_ + tid];
        float hn = fmaf(u, hold, (1.0f - u) * n);
        s_h[p * H_ + tid] = hn;                                  // h_new in place
        g_h[(b * P_ + pbase + p) * H_ + tid] = hn;
    }
    __syncthreads();

    // ---- enc (tid<128) and prior (tid>=128) projections ----
    if (tid < 128) {
        float acc[16];
        float bb = b_enc[tid];
#pragma unroll
        for (int p = 0; p < 16; ++p) acc[p] = bb;
        for (int k = 0; k < H_; ++k) {
            float w = W_enc[k * 128 + tid];
#pragma unroll
            for (int p = 0; p < 16; ++p) acc[p] = fmaf(w, s_h[p * H_ + k], acc[p]);
        }
#pragma unroll
        for (int p = 0; p < 16; ++p) s_enc[p * 128 + tid] = acc[p];
    } else {
        int j = tid - 128;
        float acc[16];
        float bb = b_pr[j];
#pragma unroll
        for (int p = 0; p < 16; ++p) acc[p] = bb;
        for (int k = 0; k < L_; ++k) {
            float w = W_pr[k * 128 + j];
#pragma unroll
            for (int p = 0; p < 16; ++p) acc[p] = fmaf(w, s_inp[p * IN_ + E_ + k], acc[p]);
        }
#pragma unroll
        for (int p = 0; p < 16; ++p) s_pr[p * 128 + j] = acc[p];
    }
    __syncthreads();

    // ---- sampling + log_alpha: warp w handles particles 2w, 2w+1 ----
    const int wid = tid >> 5, lane = tid & 31;
    const unsigned ks0 = g_keys[t * 4 + 0], ks1 = g_keys[t * 4 + 1];
    const float y0 = y[(b * T_ + t) * D_ + 0];
    const float y1 = y[(b * T_ + t) * D_ + 1];

    for (int pi = 0; pi < 2; ++pi) {
        int p = wid * 2 + pi;
        int gp = b * P_ + pbase + p;
        float part = 0.0f;
#pragma unroll
        for (int hh = 0; hh < 2; ++hh) {
            int l = lane + hh * 32;
            float mu_po = s_enc[p * 128 + l];
            float sg_po = softplus_j(s_enc[p * 128 + 64 + l] + SPB_);
            float eps = normal_draw(ks0, ks1, (unsigned)(gp * L_ + l));
            float z = fmaf(sg_po, eps, mu_po);
            s_znew[p * L_ + l] = z;
            g_znew[gp * L_ + l] = z;
            float mu_pr = s_pr[p * 128 + l];
            float sg_pr = softplus_j(s_pr[p * 128 + 64 + l] + SPB_);
            part += nlp(z, mu_pr, sg_pr) - nlp(z, mu_po, sg_po);
        }
#pragma unroll
        for (int off = 16; off; off >>= 1) part += __shfl_down_sync(0xffffffffu, part, off);
        __syncwarp();

        // decoder: 4 outputs, partial per lane over l = lane, lane+32
        float d0 = 0.f, d1 = 0.f, d2 = 0.f, d3 = 0.f;
#pragma unroll
        for (int hh = 0; hh < 2; ++hh) {
            int l = lane + hh * 32;
            float zv = s_znew[p * L_ + l];
            d0 = fmaf(zv, W_dec[l * 4 + 0], d0);
            d1 = fmaf(zv, W_dec[l * 4 + 1], d1);
            d2 = fmaf(zv, W_dec[l * 4 + 2], d2);
            d3 = fmaf(zv, W_dec[l * 4 + 3], d3);
        }
#pragma unroll
        for (int off = 16; off; off >>= 1) {
            d0 += __shfl_down_sync(0xffffffffu, d0, off);
            d1 += __shfl_down_sync(0xffffffffu, d1, off);
            d2 += __shfl_down_sync(0xffffffffu, d2, off);
            d3 += __shfl_down_sync(0xffffffffu, d3, off);
        }
        if (lane == 0) {
            float la = part;
            float mu0 = d0 + b_dec[0], mu1 = d1 + b_dec[1];
            float sgd0 = softplus_j(d2 + b_dec[2] + SPB_);
            float sgd1 = softplus_j(d3 + b_dec[3] + SPB_);
            la += nlp(y0, mu0, sgd0) + nlp(y1, mu1, sgd1);
            g_la[gp] = la;
        }
    }
}

// ---------------- per-step batch kernel: logsumexp / ESS / resample ----------------
__global__ void __launch_bounds__(128)
k_batch(float* __restrict__ out, int t) {
    __shared__ float s_lw[P_];
    __shared__ float red[P_];
    __shared__ float s_bcast[2];   // [1]=need flag

    const int b = blockIdx.x;
    const int p = threadIdx.x;

    float lpp = g_lw[b * P_ + p] + g_la[b * P_ + p];

    // max
    red[p] = lpp; __syncthreads();
#pragma unroll
    for (int s = 64; s; s >>= 1) { if (p < s) red[p] = fmaxf(red[p], red[p + s]); __syncthreads(); }
    float mx = red[0]; __syncthreads();
    // sum exp
    red[p] = expf(lpp - mx); __syncthreads();
#pragma unroll
    for (int s = 64; s; s >>= 1) { if (p < s) red[p] += red[p + s]; __syncthreads(); }
    float lse = logf(red[0]) + mx; __syncthreads();

    float lw = lpp - lse;
    s_lw[p] = lw;

    // ESS: -logsumexp(2*lw)
    red[p] = 2.0f * lw; __syncthreads();
#pragma unroll
    for (int s = 64; s; s >>= 1) { if (p < s) red[p] = fmaxf(red[p], red[p + s]); __syncthreads(); }
    float m2 = red[0]; __syncthreads();
    red[p] = expf(2.0f * lw - m2); __syncthreads();
#pragma unroll
    for (int s = 64; s; s >>= 1) { if (p < s) red[p] += red[p + s]; __syncthreads(); }
    if (p == 0) {
        float log_ess = -(logf(red[0]) + m2);
        s_bcast[1] = (expf(log_ess) < 64.0f) ? 1.0f : 0.0f;
        float lpn = g_lp[b] + lse;
        g_lp[b] = lpn;
        if (t == T_ - 1) out[b] = lpn;
    }
    __syncthreads();
    bool need = (s_bcast[1] != 0.0f);

    if (need) {
        // categorical via gumbel argmax; idx[b,p] = argmax_j gumbel[(p*B+b)*P+j] + lw[j]
        const unsigned kr0 = g_keys[t * 4 + 2], kr1 = g_keys[t * 4 + 3];
        unsigned base = ((unsigned)p * B_ + (unsigned)b) * P_;
        int best = 0;
        float bestv = -3.4e38f;
        for (int j = 0; j < P_; ++j) {
            float v = gumbel_draw(kr0, kr1, base + (unsigned)j) + s_lw[j];
            if (v > bestv) { bestv = v; best = j; }
        }
        const float4* src = (const float4*)&g_znew[(b * P_ + best) * L_];
        float4* dst = (float4*)&g_z[(b * P_ + p) * L_];
#pragma unroll
        for (int i = 0; i < L_ / 4; ++i) dst[i] = src[i];
        g_lw[b * P_ + p] = -LOGP_;
    } else {
        const float4* src = (const float4*)&g_znew[(b * P_ + p) * L_];
        float4* dst = (float4*)&g_z[(b * P_ + p) * L_];
#pragma unroll
        for (int i = 0; i < L_ / 4; ++i) dst[i] = src[i];
        g_lw[b * P_ + p] = lw;
    }
}

// ---------------- launch ----------------
extern "C" void kernel_launch(void* const* d_in, const int* in_sizes, int n_in,
                              void* d_out, int out_size) {
    const float* x     = (const float*)d_in[0];
    const float* y     = (const float*)d_in[1];
    const float* W_emb = (const float*)d_in[2];
    const float* b_emb = (const float*)d_in[3];
    const float* W_ih  = (const float*)d_in[4];
    const float* W_hh  = (const float*)d_in[5];
    const float* b_ih  = (const float*)d_in[6];
    const float* b_hh  = (const float*)d_in[7];
    const float* W_enc = (const float*)d_in[8];
    const float* b_enc = (const float*)d_in[9];
    const float* W_pr  = (const float*)d_in[10];
    const float* b_pr  = (const float*)d_in[11];
    const float* W_dec = (const float*)d_in[12];
    const float* b_dec = (const float*)d_in[13];
    float* out = (float*)d_out;

    k_setup<<<1024, 256>>>(x, W_emb, b_emb, W_ih, W_hh);
    k_keys<<<1, 1>>>();
    for (int t = 0; t < T_; ++t) {
        k_particle<<<BP_ / 16, 256>>>(y, b_ih, b_hh, W_enc, b_enc, W_pr, b_pr, W_dec, b_dec, t);
        k_batch<<<B_, P_>>>(out, t);
    }
}

// round 4
// speedup vs baseline: 1.9711x; 1.9711x over previous
#include <cuda_runtime.h>
#include <cstdint>

// Problem dims
#define B_   32
#define T_   128
#define D_   2
#define E_   64
#define L_   64
#define H_   256
#define P_   128
#define BP_  4096      // B*P
#define INP_ 132       // E+L+D padded 130 -> 132
#define CH_IH 33       // 132/4 float4 chunks
#define CH_HH 64       // 256/4
#define CH_EN 64       // 256/4
#define CH_PR 16       // 64/4

#define SPB_      0.5413248538970947f
#define HALF_L2PI 0.9189385332046727f
#define LOGP_     4.852030263919617f   // log(128)

// ---------------- persistent device state ----------------
__device__ float4 g_Wih2[CH_IH * 768];   // [c][j] packed: float4 = W_ih[j][4c..4c+3]
__device__ float4 g_Whh2[CH_HH * 768];   // [c][j]
__device__ float4 g_Wenc2[CH_EN * 128];  // [c][j]
__device__ float4 g_Wpr2[CH_PR * 128];   // [c][j]
__device__ float g_z[BP_ * L_];          // carry z (post-resample)
__device__ float g_znew[BP_ * L_];       // z_new pre-resample
__device__ float g_h[BP_ * H_];
__device__ float g_la[BP_];
__device__ float g_lw[BP_];
__device__ float g_lp[B_];
__device__ float g_embed[B_ * T_ * E_];
__device__ unsigned g_keys[T_ * 4];      // per-step {samp0,samp1,res0,res1}

// ---------------- threefry-2x32 (matches JAX partitionable) ----------------
__device__ __forceinline__ void tf2x32(unsigned k0, unsigned k1,
                                       unsigned x0, unsigned x1,
                                       unsigned& o0, unsigned& o1) {
    unsigned ks2 = k0 ^ k1 ^ 0x1BD11BDAu;
    x0 += k0; x1 += k1;
#define TF_RND(r) { x0 += x1; x1 = (x1 << (r)) | (x1 >> (32 - (r))); x1 ^= x0; }
    TF_RND(13) TF_RND(15) TF_RND(26) TF_RND(6)   x0 += k1;  x1 += ks2 + 1u;
    TF_RND(17) TF_RND(29) TF_RND(16) TF_RND(24)  x0 += ks2; x1 += k0 + 2u;
    TF_RND(13) TF_RND(15) TF_RND(26) TF_RND(6)   x0 += k0;  x1 += k1 + 3u;
    TF_RND(17) TF_RND(29) TF_RND(16) TF_RND(24)  x0 += k1;  x1 += ks2 + 4u;
    TF_RND(13) TF_RND(15) TF_RND(26) TF_RND(6)   x0 += ks2; x1 += k0 + 5u;
#undef TF_RND
    o0 = x0; o1 = x1;
}

__device__ __forceinline__ unsigned rbits32(unsigned k0, unsigned k1, unsigned i) {
    unsigned o0, o1;
    tf2x32(k0, k1, 0u, i, o0, o1);
    return o0 ^ o1;
}

__device__ __forceinline__ float bits_to_u01(unsigned bits) {
    return __uint_as_float((bits >> 9) | 0x3f800000u) - 1.0f;
}

// XLA ErfInv float32 polynomial
__device__ __forceinline__ float erfinv_x(float x) {
    float w = -log1pf(-x * x);
    float p;
    if (w < 5.0f) {
        w -= 2.5f;
        p = 2.81022636e-08f;
        p = fmaf(p, w, 3.43273939e-07f);
        p = fmaf(p, w, -3.5233877e-06f);
        p = fmaf(p, w, -4.39150654e-06f);
        p = fmaf(p, w, 0.00021858087f);
        p = fmaf(p, w, -0.00125372503f);
        p = fmaf(p, w, -0.00417768164f);
        p = fmaf(p, w, 0.246640727f);
        p = fmaf(p, w, 1.50140941f);
    } else {
        w = sqrtf(w) - 3.0f;
        p = -0.000200214257f;
        p = fmaf(p, w, 0.000100950558f);
        p = fmaf(p, w, 0.00134934322f);
        p = fmaf(p, w, -0.00367342844f);
        p = fmaf(p, w, 0.00573950773f);
        p = fmaf(p, w, -0.0076224613f);
        p = fmaf(p, w, 0.00943887047f);
        p = fmaf(p, w, 1.00167406f);
        p = fmaf(p, w, 2.83297682f);
    }
    return p * x;
}

__device__ __forceinline__ float normal_draw(unsigned k0, unsigned k1, unsigned i) {
    float f = bits_to_u01(rbits32(k0, k1, i));
    const float lo = -0.99999994039535522f;
    float u = fmaxf(lo, fmaf(f, 2.0f, lo));
    return 1.41421356f * erfinv_x(u);
}

__device__ __forceinline__ float gumbel_draw(unsigned k0, unsigned k1, unsigned i) {
    float f = bits_to_u01(rbits32(k0, k1, i));
    const float tiny = 1.17549435e-38f;
    float u = fmaxf(tiny, f + tiny);
    return -logf(-logf(u));
}

__device__ __forceinline__ float softplus_j(float x) {
    return fmaxf(x, 0.0f) + log1pf(expf(-fabsf(x)));
}

__device__ __forceinline__ float nlp(float x, float mu, float sig) {
    float t = (x - mu) / sig;
    return fmaf(-0.5f * t, t, -logf(sig) - HALF_L2PI);
}

// ---------------- setup: zero state, pack weights, embed, key chain ----------------
__global__ void k_setup(const float* __restrict__ x, const float* __restrict__ W_emb,
                        const float* __restrict__ b_emb, const float* __restrict__ W_ih,
                        const float* __restrict__ W_hh, const float* __restrict__ W_enc,
                        const float* __restrict__ W_pr) {
    if (blockIdx.x == 0 && threadIdx.x == 0) {
        unsigned k0 = 0u, k1 = 42u;
        for (int t = 0; t < T_; ++t) {
            unsigned n0, n1, s0, s1, r0, r1;
            tf2x32(k0, k1, 0u, 0u, n0, n1);   // carry
            tf2x32(k0, k1, 0u, 1u, s0, s1);   // k_samp
            tf2x32(k0, k1, 0u, 2u, r0, r1);   // k_res
            g_keys[t * 4 + 0] = s0; g_keys[t * 4 + 1] = s1;
            g_keys[t * 4 + 2] = r0; g_keys[t * 4 + 3] = r1;
            k0 = n0; k1 = n1;
        }
    }
    const int N1 = BP_ * H_, N2 = BP_ * L_, N3 = BP_, N4 = B_, N5 = B_ * T_ * E_;
    const int N6 = CH_IH * 768, N7 = CH_HH * 768, N8 = CH_EN * 128, N9 = CH_PR * 128;
    const int total = N1 + N2 + N3 + N4 + N5 + N6 + N7 + N8 + N9;
    int stride = gridDim.x * blockDim.x;
    for (int i = blockIdx.x * blockDim.x + threadIdx.x; i < total; i += stride) {
        int r = i;
        if (r < N1) { g_h[r] = 0.0f; continue; }  r -= N1;
        if (r < N2) { g_z[r] = 0.0f; continue; }  r -= N2;
        if (r < N3) { g_lw[r] = 0.0f; continue; } r -= N3;
        if (r < N4) { g_lp[r] = 0.0f; continue; } r -= N4;
        if (r < N5) {
            int bt = r >> 6, e = r & 63;
            g_embed[r] = fmaf(x[bt * 2], W_emb[e], x[bt * 2 + 1] * W_emb[E_ + e]) + b_emb[e];
            continue;
        } r -= N5;
        if (r < N6) {   // W_ih: [768][130] -> [c][j] float4, zero-pad k>=130
            int c = r / 768, j = r % 768, k = 4 * c;
            float4 v;
            v.x = (k + 0 < 130) ? W_ih[j * 130 + k + 0] : 0.0f;
            v.y = (k + 1 < 130) ? W_ih[j * 130 + k + 1] : 0.0f;
            v.z = (k + 2 < 130) ? W_ih[j * 130 + k + 2] : 0.0f;
            v.w = (k + 3 < 130) ? W_ih[j * 130 + k + 3] : 0.0f;
            g_Wih2[r] = v;
            continue;
        } r -= N6;
        if (r < N7) {   // W_hh: [768][256] -> [c][j] float4
            int c = r / 768, j = r % 768, k = 4 * c;
            float4 v;
            v.x = W_hh[j * 256 + k + 0]; v.y = W_hh[j * 256 + k + 1];
            v.z = W_hh[j * 256 + k + 2]; v.w = W_hh[j * 256 + k + 3];
            g_Whh2[r] = v;
            continue;
        } r -= N7;
        if (r < N8) {   // W_enc: [256][128] (k-major) -> [c][j] float4
            int c = r / 128, j = r % 128, k = 4 * c;
            float4 v;
            v.x = W_enc[(k + 0) * 128 + j]; v.y = W_enc[(k + 1) * 128 + j];
            v.z = W_enc[(k + 2) * 128 + j]; v.w = W_enc[(k + 3) * 128 + j];
            g_Wenc2[r] = v;
            continue;
        } r -= N8;
        {               // W_pr: [64][128] -> [c][j] float4
            int c = r / 128, j = r % 128, k = 4 * c;
            float4 v;
            v.x = W_pr[(k + 0) * 128 + j]; v.y = W_pr[(k + 1) * 128 + j];
            v.z = W_pr[(k + 2) * 128 + j]; v.w = W_pr[(k + 3) * 128 + j];
            g_Wpr2[r] = v;
        }
    }
}

// ---------------- per-step particle kernel: 16 particles / 256-thread block ----------------
__global__ void __launch_bounds__(256, 2)
k_particle(const float* __restrict__ y,
           const float* __restrict__ b_ih, const float* __restrict__ b_hh,
           const float* __restrict__ b_enc, const float* __restrict__ b_pr,
           const float* __restrict__ W_dec, const float* __restrict__ b_dec,
           int t) {
    __shared__ float s_inp[16 * INP_];   // [p][132], z at 64..127
    __shared__ float s_h[16 * H_];       // [p][256], overwritten with h_new
    __shared__ float s_enc[16 * 128];
    __shared__ float s_pr[16 * 128];
    __shared__ float s_znew[16 * L_];

    const int bid = blockIdx.x;
    const int b = bid >> 3;
    const int pbase = (bid & 7) << 4;
    const int tid = threadIdx.x;

    // ---- load inputs (s_inp index i == p*132 + k) ----
    for (int i = tid; i < 16 * INP_; i += 256) {
        int p = i / INP_, k = i - p * INP_;
        float v = 0.0f;
        if (k < 64)       v = g_embed[(b * T_ + t) * E_ + k];
        else if (k < 128) v = g_z[(b * P_ + pbase + p) * L_ + (k - 64)];
        else if (k < 130) v = y[(b * T_ + t) * D_ + (k - 128)];
        s_inp[i] = v;
    }
    for (int i = tid; i < 16 * H_; i += 256) {
        int p = i >> 8, k = i & 255;
        s_h[p * H_ + k] = g_h[(b * P_ + pbase + p) * H_ + k];
    }
    __syncthreads();

    // ---- fused GEMMs: accR = (ir+hr), accU = (iz+hz), aI2 = inn, aH2 = hn ----
    float accR[16], accU[16], aI2[16], aH2[16];
    {
        float brr = b_ih[tid] + b_hh[tid];
        float buu = b_ih[tid + 256] + b_hh[tid + 256];
        float bi2 = b_ih[tid + 512];
        float bh2 = b_hh[tid + 512];
#pragma unroll
        for (int p = 0; p < 16; ++p) { accR[p] = brr; accU[p] = buu; aI2[p] = bi2; aH2[p] = bh2; }
    }
    const float4* S4 = (const float4*)s_inp;  // [p][33]
    const float4* H4 = (const float4*)s_h;    // [p][64]

#pragma unroll 2
    for (int c = 0; c < CH_IH; ++c) {
        float4 w0 = g_Wih2[c * 768 + tid];
        float4 w1 = g_Wih2[c * 768 + tid + 256];
        float4 w2 = g_Wih2[c * 768 + tid + 512];
#pragma unroll
        for (int p = 0; p < 16; ++p) {
            float4 xv = S4[p * CH_IH + c];
            accR[p] = fmaf(w0.x, xv.x, accR[p]); accR[p] = fmaf(w0.y, xv.y, accR[p]);
            accR[p] = fmaf(w0.z, xv.z, accR[p]); accR[p] = fmaf(w0.w, xv.w, accR[p]);
            accU[p] = fmaf(w1.x, xv.x, accU[p]); accU[p] = fmaf(w1.y, xv.y, accU[p]);
            accU[p] = fmaf(w1.z, xv.z, accU[p]); accU[p] = fmaf(w1.w, xv.w, accU[p]);
            aI2[p] = fmaf(w2.x, xv.x, aI2[p]);   aI2[p] = fmaf(w2.y, xv.y, aI2[p]);
            aI2[p] = fmaf(w2.z, xv.z, aI2[p]);   aI2[p] = fmaf(w2.w, xv.w, aI2[p]);
        }
    }
#pragma unroll 2
    for (int c = 0; c < CH_HH; ++c) {
        float4 w0 = g_Whh2[c * 768 + tid];
        float4 w1 = g_Whh2[c * 768 + tid + 256];
        float4 w2 = g_Whh2[c * 768 + tid + 512];
#pragma unroll
        for (int p = 0; p < 16; ++p) {
            float4 xv = H4[p * CH_HH + c];
            accR[p] = fmaf(w0.x, xv.x, accR[p]); accR[p] = fmaf(w0.y, xv.y, accR[p]);
            accR[p] = fmaf(w0.z, xv.z, accR[p]); accR[p] = fmaf(w0.w, xv.w, accR[p]);
            accU[p] = fmaf(w1.x, xv.x, accU[p]); accU[p] = fmaf(w1.y, xv.y, accU[p]);
            accU[p] = fmaf(w1.z, xv.z, accU[p]); accU[p] = fmaf(w1.w, xv.w, accU[p]);
            aH2[p] = fmaf(w2.x, xv.x, aH2[p]);   aH2[p] = fmaf(w2.y, xv.y, aH2[p]);
            aH2[p] = fmaf(w2.z, xv.z, aH2[p]);   aH2[p] = fmaf(w2.w, xv.w, aH2[p]);
        }
    }
    __syncthreads();   // all H4 reads done before in-place overwrite

    // ---- GRU gates (thread owns hidden unit j = tid) ----
#pragma unroll
    for (int p = 0; p < 16; ++p) {
        float r = 1.0f / (1.0f + expf(-accR[p]));
        float u = 1.0f / (1.0f + expf(-accU[p]));
        float n = tanhf(fmaf(r, aH2[p], aI2[p]));
        float hold = s_h[p * H_ + tid];
        float hn = fmaf(u, hold, (1.0f - u) * n);
        s_h[p * H_ + tid] = hn;
        g_h[(b * P_ + pbase + p) * H_ + tid] = hn;
    }
    __syncthreads();

    // ---- enc (tid<128) and prior (tid>=128) projections ----
    if (tid < 128) {
        float acc[16];
        float bb = b_enc[tid];
#pragma unroll
        for (int p = 0; p < 16; ++p) acc[p] = bb;
#pragma unroll 2
        for (int c = 0; c < CH_EN; ++c) {
            float4 w = g_Wenc2[c * 128 + tid];
#pragma unroll
            for (int p = 0; p < 16; ++p) {
                float4 xv = H4[p * CH_HH + c];
                acc[p] = fmaf(w.x, xv.x, acc[p]); acc[p] = fmaf(w.y, xv.y, acc[p]);
                acc[p] = fmaf(w.z, xv.z, acc[p]); acc[p] = fmaf(w.w, xv.w, acc[p]);
            }
        }
#pragma unroll
        for (int p = 0; p < 16; ++p) s_enc[p * 128 + tid] = acc[p];
    } else {
        int j = tid - 128;
        float acc[16];
        float bb = b_pr[j];
#pragma unroll
        for (int p = 0; p < 16; ++p) acc[p] = bb;
#pragma unroll 2
        for (int c = 0; c < CH_PR; ++c) {
            float4 w = g_Wpr2[c * 128 + j];
#pragma unroll
            for (int p = 0; p < 16; ++p) {
                float4 xv = S4[p * CH_IH + 16 + c];   // z part: floats 64..127
                acc[p] = fmaf(w.x, xv.x, acc[p]); acc[p] = fmaf(w.y, xv.y, acc[p]);
                acc[p] = fmaf(w.z, xv.z, acc[p]); acc[p] = fmaf(w.w, xv.w, acc[p]);
            }
        }
#pragma unroll
        for (int p = 0; p < 16; ++p) s_pr[p * 128 + j] = acc[p];
    }
    __syncthreads();

    // ---- sampling + log_alpha: warp w handles particles 2w, 2w+1 ----
    const int wid = tid >> 5, lane = tid & 31;
    const unsigned ks0 = g_keys[t * 4 + 0], ks1 = g_keys[t * 4 + 1];
    const float y0 = y[(b * T_ + t) * D_ + 0];
    const float y1 = y[(b * T_ + t) * D_ + 1];

    for (int pi = 0; pi < 2; ++pi) {
        int p = wid * 2 + pi;
        int gp = b * P_ + pbase + p;
        float part = 0.0f;
#pragma unroll
        for (int hh = 0; hh < 2; ++hh) {
            int l = lane + hh * 32;
            float mu_po = s_enc[p * 128 + l];
            float sg_po = softplus_j(s_enc[p * 128 + 64 + l] + SPB_);
            float eps = normal_draw(ks0, ks1, (unsigned)(gp * L_ + l));
            float z = fmaf(sg_po, eps, mu_po);
            s_znew[p * L_ + l] = z;
            g_znew[gp * L_ + l] = z;
            g_z[gp * L_ + l] = z;          // default (no-resample) carry
            float mu_pr = s_pr[p * 128 + l];
            float sg_pr = softplus_j(s_pr[p * 128 + 64 + l] + SPB_);
            part += nlp(z, mu_pr, sg_pr) - nlp(z, mu_po, sg_po);
        }
#pragma unroll
        for (int off = 16; off; off >>= 1) part += __shfl_down_sync(0xffffffffu, part, off);
        __syncwarp();

        float d0 = 0.f, d1 = 0.f, d2 = 0.f, d3 = 0.f;
#pragma unroll
        for (int hh = 0; hh < 2; ++hh) {
            int l = lane + hh * 32;
            float zv = s_znew[p * L_ + l];
            d0 = fmaf(zv, W_dec[l * 4 + 0], d0);
            d1 = fmaf(zv, W_dec[l * 4 + 1], d1);
            d2 = fmaf(zv, W_dec[l * 4 + 2], d2);
            d3 = fmaf(zv, W_dec[l * 4 + 3], d3);
        }
#pragma unroll
        for (int off = 16; off; off >>= 1) {
            d0 += __shfl_down_sync(0xffffffffu, d0, off);
            d1 += __shfl_down_sync(0xffffffffu, d1, off);
            d2 += __shfl_down_sync(0xffffffffu, d2, off);
            d3 += __shfl_down_sync(0xffffffffu, d3, off);
        }
        if (lane == 0) {
            float la = part;
            float mu0 = d0 + b_dec[0], mu1 = d1 + b_dec[1];
            float sgd0 = softplus_j(d2 + b_dec[2] + SPB_);
            float sgd1 = softplus_j(d3 + b_dec[3] + SPB_);
            la += nlp(y0, mu0, sgd0) + nlp(y1, mu1, sgd1);
            g_la[gp] = la;
        }
    }
}

// ---------------- per-step batch kernel: logsumexp / ESS / resample ----------------
__global__ void __launch_bounds__(256)
k_batch(float* __restrict__ out, int t) {
    __shared__ float s_lw[P_];
    __shared__ float s_r1[4], s_r2[4], s_r3[4], s_r4[4];
    __shared__ float s_flag;

    const int b = blockIdx.x;
    const int tid = threadIdx.x;
    const int lane = tid & 31, w = tid >> 5;

    float lpp = 0.0f;
    if (tid < 128) {
        lpp = g_lw[b * P_ + tid] + g_la[b * P_ + tid];
        float m = lpp;
#pragma unroll
        for (int off = 16; off; off >>= 1) m = fmaxf(m, __shfl_xor_sync(0xffffffffu, m, off));
        if (lane == 0) s_r1[w] = m;
    }
    __syncthreads();
    float mx = fmaxf(fmaxf(s_r1[0], s_r1[1]), fmaxf(s_r1[2], s_r1[3]));
    if (tid < 128) {
        float e = expf(lpp - mx);
#pragma unroll
        for (int off = 16; off; off >>= 1) e += __shfl_xor_sync(0xffffffffu, e, off);
        if (lane == 0) s_r2[w] = e;
    }
    __syncthreads();
    float lse = logf(s_r2[0] + s_r2[1] + s_r2[2] + s_r2[3]) + mx;

    float lw = 0.0f;
    if (tid < 128) {
        lw = lpp - lse;
        s_lw[tid] = lw;
        float a = 2.0f * lw;
#pragma unroll
        for (int off = 16; off; off >>= 1) a = fmaxf(a, __shfl_xor_sync(0xffffffffu, a, off));
        if (lane == 0) s_r3[w] = a;
    }
    __syncthreads();
    float m2 = fmaxf(fmaxf(s_r3[0], s_r3[1]), fmaxf(s_r3[2], s_r3[3]));
    if (tid < 128) {
        float e = expf(2.0f * lw - m2);
#pragma unroll
        for (int off = 16; off; off >>= 1) e += __shfl_xor_sync(0xffffffffu, e, off);
        if (lane == 0) s_r4[w] = e;
    }
    __syncthreads();
    if (tid == 0) {
        float log_ess = -(logf(s_r4[0] + s_r4[1] + s_r4[2] + s_r4[3]) + m2);
        s_flag = (expf(log_ess) < 64.0f) ? 1.0f : 0.0f;
        float lpn = g_lp[b] + lse;
        g_lp[b] = lpn;
        if (t == T_ - 1) out[b] = lpn;
    }
    __syncthreads();
    bool need = (s_flag != 0.0f);

    if (need) {
        // categorical via gumbel argmax, warp per particle, 16 particles/warp
        const unsigned kr0 = g_keys[t * 4 + 2], kr1 = g_keys[t * 4 + 3];
        for (int i = 0; i < 16; ++i) {
            int p = w * 16 + i;
            unsigned base = ((unsigned)p * B_ + (unsigned)b) * P_;
            float bv = -3.4e38f;
            int bj = 0;
#pragma unroll
            for (int jj = 0; jj < 4; ++jj) {
                int j = lane * 4 + jj;
                float v = gumbel_draw(kr0, kr1, base + (unsigned)j) + s_lw[j];
                if (v > bv) { bv = v; bj = j; }
            }
#pragma unroll
            for (int off = 16; off; off >>= 1) {
                float ov = __shfl_xor_sync(0xffffffffu, bv, off);
                int   oj = __shfl_xor_sync(0xffffffffu, bj, off);
                if (ov > bv || (ov == bv && oj < bj)) { bv = ov; bj = oj; }
            }
            // gather z: 16 float4 per particle
            if (lane < 16) {
                const float4* src = (const float4*)&g_znew[(b * P_ + bj) * L_];
                float4* dst = (float4*)&g_z[(b * P_ + p) * L_];
                dst[lane] = src[lane];
            }
            if (lane == 0) g_lw[b * P_ + p] = -LOGP_;
        }
    } else {
        if (tid < 128) g_lw[b * P_ + tid] = lw;   // g_z already holds z_new
    }
}

// ---------------- launch ----------------
extern "C" void kernel_launch(void* const* d_in, const int* in_sizes, int n_in,
                              void* d_out, int out_size) {
    const float* x     = (const float*)d_in[0];
    const float* y     = (const float*)d_in[1];
    const float* W_emb = (const float*)d_in[2];
    const float* b_emb = (const float*)d_in[3];
    const float* W_ih  = (const float*)d_in[4];
    const float* W_hh  = (const float*)d_in[5];
    const float* b_ih  = (const float*)d_in[6];
    const float* b_hh  = (const float*)d_in[7];
    const float* W_enc = (const float*)d_in[8];
    const float* b_enc = (const float*)d_in[9];
    const float* W_pr  = (const float*)d_in[10];
    const float* b_pr  = (const float*)d_in[11];
    const float* W_dec = (const float*)d_in[12];
    const float* b_dec = (const float*)d_in[13];
    float* out = (float*)d_out;

    k_setup<<<1024, 256>>>(x, W_emb, b_emb, W_ih, W_hh, W_enc, W_pr);
    for (int t = 0; t < T_; ++t) {
        k_particle<<<BP_ / 16, 256>>>(y, b_ih, b_hh, b_enc, b_pr, W_dec, b_dec, t);
        k_batch<<<B_, 256>>>(out, t);
    }
}

// round 5
// speedup vs baseline: 2.2617x; 1.1474x over previous
#include <cuda_runtime.h>
#include <cstdint>

// Problem dims
#define B_   32
#define T_   128
#define D_   2
#define E_   64
#define L_   64
#define H_   256
#define P_   128
#define BP_  4096      // B*P

#define SPB_      0.5413248538970947f
#define HALF_L2PI 0.9189385332046727f
#define LOGP_     4.852030263919617f   // log(128)

typedef unsigned long long ull;

// ---------------- persistent device state ----------------
__device__ float4 g_Wihz4[16 * 768];   // W_ih cols 64..127 (z part): [c][j], float4 = k 4c..4c+3
__device__ float4 g_Whh4[64 * 768];    // [c][j]
__device__ float4 g_Wenc4[64 * 128];   // [c][j]
__device__ float4 g_Wpr4[16 * 128];    // [c][j]
__device__ float g_Wxy[66 * 768];      // W_ih cols {0..63,128,129} transposed: [k][j]
__device__ float g_gixy[B_ * 768];     // per-batch x/y part of gi (incl b_ih)
__device__ float g_z[BP_ * L_];        // carry z (post-resample), [gp][l]
__device__ float g_znew[BP_ * L_];     // z_new pre-resample
__device__ float g_hT[BP_ * H_];       // transposed per block: [block(256)][k(256)][p(16)]
__device__ float g_la[BP_];
__device__ float g_lw[BP_];
__device__ float g_lp[B_];
__device__ float g_embed[B_ * T_ * E_];
__device__ unsigned g_keys[T_ * 4];    // per-step {samp0,samp1,res0,res1}

// ---------------- packed f32x2 helpers ----------------
__device__ __forceinline__ ull pk2(float v) {
    ull r; asm("mov.b64 %0, {%1, %1};" : "=l"(r) : "f"(v)); return r;
}
__device__ __forceinline__ void upk2(ull v, float& a, float& b) {
    asm("mov.b64 {%0, %1}, %2;" : "=f"(a), "=f"(b) : "l"(v));
}
#define FMA2(acc, w, x) asm("fma.rn.f32x2 %0, %1, %2, %0;" : "+l"(acc) : "l"(w), "l"(x))

// ---------------- threefry-2x32 (JAX partitionable) ----------------
__device__ __forceinline__ void tf2x32(unsigned k0, unsigned k1,
                                       unsigned x0, unsigned x1,
                                       unsigned& o0, unsigned& o1) {
    unsigned ks2 = k0 ^ k1 ^ 0x1BD11BDAu;
    x0 += k0; x1 += k1;
#define TF_RND(r) { x0 += x1; x1 = (x1 << (r)) | (x1 >> (32 - (r))); x1 ^= x0; }
    TF_RND(13) TF_RND(15) TF_RND(26) TF_RND(6)   x0 += k1;  x1 += ks2 + 1u;
    TF_RND(17) TF_RND(29) TF_RND(16) TF_RND(24)  x0 += ks2; x1 += k0 + 2u;
    TF_RND(13) TF_RND(15) TF_RND(26) TF_RND(6)   x0 += k0;  x1 += k1 + 3u;
    TF_RND(17) TF_RND(29) TF_RND(16) TF_RND(24)  x0 += k1;  x1 += ks2 + 4u;
    TF_RND(13) TF_RND(15) TF_RND(26) TF_RND(6)   x0 += ks2; x1 += k0 + 5u;
#undef TF_RND
    o0 = x0; o1 = x1;
}

__device__ __forceinline__ unsigned rbits32(unsigned k0, unsigned k1, unsigned i) {
    unsigned o0, o1;
    tf2x32(k0, k1, 0u, i, o0, o1);
    return o0 ^ o1;
}

__device__ __forceinline__ float bits_to_u01(unsigned bits) {
    return __uint_as_float((bits >> 9) | 0x3f800000u) - 1.0f;
}

// XLA ErfInv float32 polynomial
__device__ __forceinline__ float erfinv_x(float x) {
    float w = -log1pf(-x * x);
    float p;
    if (w < 5.0f) {
        w -= 2.5f;
        p = 2.81022636e-08f;
        p = fmaf(p, w, 3.43273939e-07f);
        p = fmaf(p, w, -3.5233877e-06f);
        p = fmaf(p, w, -4.39150654e-06f);
        p = fmaf(p, w, 0.00021858087f);
        p = fmaf(p, w, -0.00125372503f);
        p = fmaf(p, w, -0.00417768164f);
        p = fmaf(p, w, 0.246640727f);
        p = fmaf(p, w, 1.50140941f);
    } else {
        w = sqrtf(w) - 3.0f;
        p = -0.000200214257f;
        p = fmaf(p, w, 0.000100950558f);
        p = fmaf(p, w, 0.00134934322f);
        p = fmaf(p, w, -0.00367342844f);
        p = fmaf(p, w, 0.00573950773f);
        p = fmaf(p, w, -0.0076224613f);
        p = fmaf(p, w, 0.00943887047f);
        p = fmaf(p, w, 1.00167406f);
        p = fmaf(p, w, 2.83297682f);
    }
    return p * x;
}

__device__ __forceinline__ float normal_draw(unsigned k0, unsigned k1, unsigned i) {
    float f = bits_to_u01(rbits32(k0, k1, i));
    const float lo = -0.99999994039535522f;
    float u = fmaxf(lo, fmaf(f, 2.0f, lo));
    return 1.41421356f * erfinv_x(u);
}

__device__ __forceinline__ float gumbel_draw(unsigned k0, unsigned k1, unsigned i) {
    float f = bits_to_u01(rbits32(k0, k1, i));
    const float tiny = 1.17549435e-38f;
    float u = fmaxf(tiny, f + tiny);
    return -logf(-logf(u));
}

__device__ __forceinline__ float softplus_j(float x) {
    return fmaxf(x, 0.0f) + log1pf(expf(-fabsf(x)));
}

__device__ __forceinline__ float nlp(float x, float mu, float sig) {
    float t = (x - mu) / sig;
    return fmaf(-0.5f * t, t, -logf(sig) - HALF_L2PI);
}

// ---------------- setup ----------------
__global__ void k_setup(const float* __restrict__ x, const float* __restrict__ y,
                        const float* __restrict__ W_emb, const float* __restrict__ b_emb,
                        const float* __restrict__ W_ih, const float* __restrict__ W_hh,
                        const float* __restrict__ W_enc, const float* __restrict__ W_pr,
                        const float* __restrict__ b_ih) {
    if (blockIdx.x == 0 && threadIdx.x == 0) {
        unsigned k0 = 0u, k1 = 42u;
        for (int t = 0; t < T_; ++t) {
            unsigned n0, n1, s0, s1, r0, r1;
            tf2x32(k0, k1, 0u, 0u, n0, n1);
            tf2x32(k0, k1, 0u, 1u, s0, s1);
            tf2x32(k0, k1, 0u, 2u, r0, r1);
            g_keys[t * 4 + 0] = s0; g_keys[t * 4 + 1] = s1;
            g_keys[t * 4 + 2] = r0; g_keys[t * 4 + 3] = r1;
            k0 = n0; k1 = n1;
        }
    }
    const int N1 = BP_ * H_;          // zero g_hT
    const int N2 = BP_ * L_;          // zero g_z
    const int N3 = BP_;               // zero g_lw
    const int N4 = B_;                // zero g_lp
    const int N5 = B_ * T_ * E_;      // embed
    const int N6 = 16 * 768;          // Wihz4
    const int N7 = 64 * 768;          // Whh4
    const int N8 = 64 * 128;          // Wenc4
    const int N9 = 16 * 128;          // Wpr4
    const int N10 = 66 * 768;         // Wxy
    const int N11 = B_ * 768;         // gixy t=0
    const int total = N1 + N2 + N3 + N4 + N5 + N6 + N7 + N8 + N9 + N10 + N11;
    int stride = gridDim.x * blockDim.x;
    for (int i = blockIdx.x * blockDim.x + threadIdx.x; i < total; i += stride) {
        int r = i;
        if (r < N1) { g_hT[r] = 0.0f; continue; } r -= N1;
        if (r < N2) { g_z[r] = 0.0f; continue; }  r -= N2;
        if (r < N3) { g_lw[r] = 0.0f; continue; } r -= N3;
        if (r < N4) { g_lp[r] = 0.0f; continue; } r -= N4;
        if (r < N5) {
            int bt = r >> 6, e = r & 63;
            g_embed[r] = fmaf(x[bt * 2], W_emb[e], x[bt * 2 + 1] * W_emb[E_ + e]) + b_emb[e];
            continue;
        } r -= N5;
        if (r < N6) {   // W_ih z-part: k = 64 + 4c
            int c = r / 768, j = r % 768, k = 64 + 4 * c;
            float4 v;
            v.x = W_ih[j * 130 + k + 0]; v.y = W_ih[j * 130 + k + 1];
            v.z = W_ih[j * 130 + k + 2]; v.w = W_ih[j * 130 + k + 3];
            g_Wihz4[r] = v;
            continue;
        } r -= N6;
        if (r < N7) {
            int c = r / 768, j = r % 768, k = 4 * c;
            float4 v;
            v.x = W_hh[j * 256 + k + 0]; v.y = W_hh[j * 256 + k + 1];
            v.z = W_hh[j * 256 + k + 2]; v.w = W_hh[j * 256 + k + 3];
            g_Whh4[r] = v;
            continue;
        } r -= N7;
        if (r < N8) {
            int c = r / 128, j = r % 128, k = 4 * c;
            float4 v;
            v.x = W_enc[(k + 0) * 128 + j]; v.y = W_enc[(k + 1) * 128 + j];
            v.z = W_enc[(k + 2) * 128 + j]; v.w = W_enc[(k + 3) * 128 + j];
            g_Wenc4[r] = v;
            continue;
        } r -= N8;
        if (r < N9) {
            int c = r / 128, j = r % 128, k = 4 * c;
            float4 v;
            v.x = W_pr[(k + 0) * 128 + j]; v.y = W_pr[(k + 1) * 128 + j];
            v.z = W_pr[(k + 2) * 128 + j]; v.w = W_pr[(k + 3) * 128 + j];
            g_Wpr4[r] = v;
            continue;
        } r -= N9;
        if (r < N10) {  // W_ih xy-part transposed
            int k = r / 768, j = r % 768;
            int ok = (k < 64) ? k : (64 + k);   // 64->128, 65->129
            g_Wxy[r] = W_ih[j * 130 + ok];
            continue;
        } r -= N10;
        {               // gixy for t=0
            int b = r / 768, j = r % 768;
            float x0 = x[(b * T_) * 2], x1 = x[(b * T_) * 2 + 1];
            float acc = b_ih[j];
            for (int k = 0; k < 64; ++k) {
                float emb = fmaf(x0, W_emb[k], x1 * W_emb[64 + k]) + b_emb[k];
                acc = fmaf(W_ih[j * 130 + k], emb, acc);
            }
            acc = fmaf(W_ih[j * 130 + 128], y[(b * T_) * 2], acc);
            acc = fmaf(W_ih[j * 130 + 129], y[(b * T_) * 2 + 1], acc);
            g_gixy[b * 768 + j] = acc;
        }
    }
}

// 24 packed FMAs for one k: 3 gates x 8 particle-pairs
#define GEMM_K3(wr2, wu2, wn2, accN, rowptr)                                   \
    {                                                                          \
        const ulonglong2* _row = (const ulonglong2*)(rowptr);                  \
        ulonglong2 _a0 = _row[0], _a1 = _row[1], _a2 = _row[2], _a3 = _row[3]; \
        FMA2(accR2[0], wr2, _a0.x); FMA2(accR2[1], wr2, _a0.y);                \
        FMA2(accR2[2], wr2, _a1.x); FMA2(accR2[3], wr2, _a1.y);                \
        FMA2(accR2[4], wr2, _a2.x); FMA2(accR2[5], wr2, _a2.y);                \
        FMA2(accR2[6], wr2, _a3.x); FMA2(accR2[7], wr2, _a3.y);                \
        FMA2(accU2[0], wu2, _a0.x); FMA2(accU2[1], wu2, _a0.y);                \
        FMA2(accU2[2], wu2, _a1.x); FMA2(accU2[3], wu2, _a1.y);                \
        FMA2(accU2[4], wu2, _a2.x); FMA2(accU2[5], wu2, _a2.y);                \
        FMA2(accU2[6], wu2, _a3.x); FMA2(accU2[7], wu2, _a3.y);                \
        FMA2(accN[0], wn2, _a0.x);  FMA2(accN[1], wn2, _a0.y);                 \
        FMA2(accN[2], wn2, _a1.x);  FMA2(accN[3], wn2, _a1.y);                 \
        FMA2(accN[4], wn2, _a2.x);  FMA2(accN[5], wn2, _a2.y);                 \
        FMA2(accN[6], wn2, _a3.x);  FMA2(accN[7], wn2, _a3.y);                 \
    }

// ---------------- per-step particle kernel: 16 particles / 256-thread block ----------------
__global__ void __launch_bounds__(256, 2)
k_particle(const float* __restrict__ y, const float* __restrict__ b_hh,
           const float* __restrict__ b_enc, const float* __restrict__ b_pr,
           const float* __restrict__ W_dec, const float* __restrict__ b_dec,
           int t) {
    __shared__ __align__(16) float s_zT[64 * 16];    // [l][p]
    __shared__ __align__(16) float s_hT[256 * 16];   // [k][p], old then new
    __shared__ float s_enc[16 * 128];
    __shared__ float s_pr[16 * 128];
    __shared__ float s_znew[16 * 64];

    const int bid = blockIdx.x;
    const int b = bid >> 3;
    const int pbase = (bid & 7) << 4;
    const int tid = threadIdx.x;

    // ---- loads: z transposed, h straight (g_hT already transposed per block) ----
    for (int i = tid; i < 1024; i += 256) {
        int p = i >> 6, l = i & 63;
        s_zT[l * 16 + p] = g_z[(b * P_ + pbase + p) * L_ + l];
    }
    {
        const float4* gh4 = (const float4*)(g_hT + bid * 4096);
        float4* sh4 = (float4*)s_hT;
        for (int i = tid; i < 1024; i += 256) sh4[i] = gh4[i];
    }
    __syncthreads();

    // ---- packed accumulators (pair = 2 particles) ----
    ull accR2[8], accU2[8], accI2[8], accH2[8];
    {
        float iR = g_gixy[b * 768 + tid] + b_hh[tid];
        float iU = g_gixy[b * 768 + 256 + tid] + b_hh[256 + tid];
        float iI = g_gixy[b * 768 + 512 + tid];
        float iH = b_hh[512 + tid];
        ull pR = pk2(iR), pU = pk2(iU), pI = pk2(iI), pH = pk2(iH);
#pragma unroll
        for (int q = 0; q < 8; ++q) { accR2[q] = pR; accU2[q] = pU; accI2[q] = pI; accH2[q] = pH; }
    }

    // ---- GEMM over z (W_ih z-part): 16 chunks ----
#pragma unroll 2
    for (int c = 0; c < 16; ++c) {
        float4 w0 = g_Wihz4[c * 768 + tid];
        float4 w1 = g_Wihz4[c * 768 + tid + 256];
        float4 w2 = g_Wihz4[c * 768 + tid + 512];
#pragma unroll
        for (int kk = 0; kk < 4; ++kk) {
            ull wr2 = pk2(((const float*)&w0)[kk]);
            ull wu2 = pk2(((const float*)&w1)[kk]);
            ull wn2 = pk2(((const float*)&w2)[kk]);
            GEMM_K3(wr2, wu2, wn2, accI2, s_zT + ((c * 4 + kk) << 4));
        }
    }
    // ---- GEMM over h (W_hh): 64 chunks ----
#pragma unroll 2
    for (int c = 0; c < 64; ++c) {
        float4 w0 = g_Whh4[c * 768 + tid];
        float4 w1 = g_Whh4[c * 768 + tid + 256];
        float4 w2 = g_Whh4[c * 768 + tid + 512];
#pragma unroll
        for (int kk = 0; kk < 4; ++kk) {
            ull wr2 = pk2(((const float*)&w0)[kk]);
            ull wu2 = pk2(((const float*)&w1)[kk]);
            ull wn2 = pk2(((const float*)&w2)[kk]);
            GEMM_K3(wr2, wu2, wn2, accH2, s_hT + ((c * 4 + kk) << 4));
        }
    }
    __syncthreads();   // all s_hT reads (old h) complete

    // ---- GRU gates: thread owns hidden unit j = tid, row tid of s_hT ----
    {
        float accR[16], accU[16], accI[16], accH[16];
#pragma unroll
        for (int q = 0; q < 8; ++q) {
            upk2(accR2[q], accR[2 * q], accR[2 * q + 1]);
            upk2(accU2[q], accU[2 * q], accU[2 * q + 1]);
            upk2(accI2[q], accI[2 * q], accI[2 * q + 1]);
            upk2(accH2[q], accH[2 * q], accH[2 * q + 1]);
        }
        float4* myrow = (float4*)(s_hT + tid * 16);
        float4 hold4[4];
#pragma unroll
        for (int q = 0; q < 4; ++q) hold4[q] = myrow[q];
        float hn[16];
#pragma unroll
        for (int p = 0; p < 16; ++p) {
            float r = 1.0f / (1.0f + expf(-accR[p]));
            float u = 1.0f / (1.0f + expf(-accU[p]));
            float n = tanhf(fmaf(r, accH[p], accI[p]));
            float hold = ((const float*)hold4)[p];
            hn[p] = fmaf(u, hold, (1.0f - u) * n);
        }
        float4* gout = (float4*)(g_hT + bid * 4096 + tid * 16);
#pragma unroll
        for (int q = 0; q < 4; ++q) {
            float4 v = make_float4(hn[4 * q], hn[4 * q + 1], hn[4 * q + 2], hn[4 * q + 3]);
            myrow[q] = v;
            gout[q] = v;
        }
    }
    __syncthreads();

    // ---- enc (tid<128, over new h) and prior (tid>=128, over z) ----
    if (tid < 128) {
        ull acc2[8];
        {
            ull pb = pk2(b_enc[tid]);
#pragma unroll
            for (int q = 0; q < 8; ++q) acc2[q] = pb;
        }
#pragma unroll 2
        for (int c = 0; c < 64; ++c) {
            float4 w = g_Wenc4[c * 128 + tid];
#pragma unroll
            for (int kk = 0; kk < 4; ++kk) {
                ull w2 = pk2(((const float*)&w)[kk]);
                const ulonglong2* row = (const ulonglong2*)(s_hT + ((c * 4 + kk) << 4));
                ulonglong2 a0 = row[0], a1 = row[1], a2 = row[2], a3 = row[3];
                FMA2(acc2[0], w2, a0.x); FMA2(acc2[1], w2, a0.y);
                FMA2(acc2[2], w2, a1.x); FMA2(acc2[3], w2, a1.y);
                FMA2(acc2[4], w2, a2.x); FMA2(acc2[5], w2, a2.y);
                FMA2(acc2[6], w2, a3.x); FMA2(acc2[7], w2, a3.y);
            }
        }
#pragma unroll
        for (int q = 0; q < 8; ++q) {
            float lo, hi;
            upk2(acc2[q], lo, hi);
            s_enc[(2 * q) * 128 + tid] = lo;
            s_enc[(2 * q + 1) * 128 + tid] = hi;
        }
    } else {
        int j = tid - 128;
        ull acc2[8];
        {
            ull pb = pk2(b_pr[j]);
#pragma unroll
            for (int q = 0; q < 8; ++q) acc2[q] = pb;
        }
#pragma unroll 2
        for (int c = 0; c < 16; ++c) {
            float4 w = g_Wpr4[c * 128 + j];
#pragma unroll
            for (int kk = 0; kk < 4; ++kk) {
                ull w2 = pk2(((const float*)&w)[kk]);
                const ulonglong2* row = (const ulonglong2*)(s_zT + ((c * 4 + kk) << 4));
                ulonglong2 a0 = row[0], a1 = row[1], a2 = row[2], a3 = row[3];
                FMA2(acc2[0], w2, a0.x); FMA2(acc2[1], w2, a0.y);
                FMA2(acc2[2], w2, a1.x); FMA2(acc2[3], w2, a1.y);
                FMA2(acc2[4], w2, a2.x); FMA2(acc2[5], w2, a2.y);
                FMA2(acc2[6], w2, a3.x); FMA2(acc2[7], w2, a3.y);
            }
        }
#pragma unroll
        for (int q = 0; q < 8; ++q) {
            float lo, hi;
            upk2(acc2[q], lo, hi);
            s_pr[(2 * q) * 128 + j] = lo;
            s_pr[(2 * q + 1) * 128 + j] = hi;
        }
    }
    __syncthreads();

    // ---- sampling + log_alpha: warp w handles particles 2w, 2w+1 ----
    const int wid = tid >> 5, lane = tid & 31;
    const unsigned ks0 = g_keys[t * 4 + 0], ks1 = g_keys[t * 4 + 1];
    const float y0 = y[(b * T_ + t) * D_ + 0];
    const float y1 = y[(b * T_ + t) * D_ + 1];

    for (int pi = 0; pi < 2; ++pi) {
        int p = wid * 2 + pi;
        int gp = b * P_ + pbase + p;
        float part = 0.0f;
#pragma unroll
        for (int hh = 0; hh < 2; ++hh) {
            int l = lane + hh * 32;
            float mu_po = s_enc[p * 128 + l];
            float sg_po = softplus_j(s_enc[p * 128 + 64 + l] + SPB_);
            float eps = normal_draw(ks0, ks1, (unsigned)(gp * L_ + l));
            float z = fmaf(sg_po, eps, mu_po);
            s_znew[p * 64 + l] = z;
            g_znew[gp * 64 + l] = z;
            g_z[gp * 64 + l] = z;          // default (no-resample) carry
            float mu_pr = s_pr[p * 128 + l];
            float sg_pr = softplus_j(s_pr[p * 128 + 64 + l] + SPB_);
            part += nlp(z, mu_pr, sg_pr) - nlp(z, mu_po, sg_po);
        }
#pragma unroll
        for (int off = 16; off; off >>= 1) part += __shfl_down_sync(0xffffffffu, part, off);
        __syncwarp();

        float d0 = 0.f, d1 = 0.f, d2 = 0.f, d3 = 0.f;
#pragma unroll
        for (int hh = 0; hh < 2; ++hh) {
            int l = lane + hh * 32;
            float zv = s_znew[p * 64 + l];
            d0 = fmaf(zv, W_dec[l * 4 + 0], d0);
            d1 = fmaf(zv, W_dec[l * 4 + 1], d1);
            d2 = fmaf(zv, W_dec[l * 4 + 2], d2);
            d3 = fmaf(zv, W_dec[l * 4 + 3], d3);
        }
#pragma unroll
        for (int off = 16; off; off >>= 1) {
            d0 += __shfl_down_sync(0xffffffffu, d0, off);
            d1 += __shfl_down_sync(0xffffffffu, d1, off);
            d2 += __shfl_down_sync(0xffffffffu, d2, off);
            d3 += __shfl_down_sync(0xffffffffu, d3, off);
        }
        if (lane == 0) {
            float la = part;
            float mu0 = d0 + b_dec[0], mu1 = d1 + b_dec[1];
            float sgd0 = softplus_j(d2 + b_dec[2] + SPB_);
            float sgd1 = softplus_j(d3 + b_dec[3] + SPB_);
            la += nlp(y0, mu0, sgd0) + nlp(y1, mu1, sgd1);
            g_la[gp] = la;
        }
    }
}

// ---------------- per-step batch kernel: logsumexp / ESS / resample / next gi_xy ----------------
__global__ void __launch_bounds__(256)
k_batch(float* __restrict__ out, const float* __restrict__ y,
        const float* __restrict__ b_ih, int t) {
    __shared__ float s_lw[P_];
    __shared__ float s_emb[66];
    __shared__ float s_r1[4], s_r2[4], s_r3[4], s_r4[4];
    __shared__ float s_flag;

    const int b = blockIdx.x;
    const int tid = threadIdx.x;
    const int lane = tid & 31, w = tid >> 5;

    // stage next step's embed + y for gi_xy
    if (t + 1 < T_) {
        if (tid < 64) s_emb[tid] = g_embed[(b * T_ + t + 1) * 64 + tid];
        else if (tid < 66) s_emb[tid] = y[(b * T_ + t + 1) * 2 + (tid - 64)];
    }

    float lpp = 0.0f;
    if (tid < 128) {
        lpp = g_lw[b * P_ + tid] + g_la[b * P_ + tid];
        float m = lpp;
#pragma unroll
        for (int off = 16; off; off >>= 1) m = fmaxf(m, __shfl_xor_sync(0xffffffffu, m, off));
        if (lane == 0) s_r1[w] = m;
    }
    __syncthreads();
    float mx = fmaxf(fmaxf(s_r1[0], s_r1[1]), fmaxf(s_r1[2], s_r1[3]));
    if (tid < 128) {
        float e = expf(lpp - mx);
#pragma unroll
        for (int off = 16; off; off >>= 1) e += __shfl_xor_sync(0xffffffffu, e, off);
        if (lane == 0) s_r2[w] = e;
    }
    __syncthreads();
    float lse = logf(s_r2[0] + s_r2[1] + s_r2[2] + s_r2[3]) + mx;

    float lw = 0.0f;
    if (tid < 128) {
        lw = lpp - lse;
        s_lw[tid] = lw;
        float a = 2.0f * lw;
#pragma unroll
        for (int off = 16; off; off >>= 1) a = fmaxf(a, __shfl_xor_sync(0xffffffffu, a, off));
        if (lane == 0) s_r3[w] = a;
    }
    __syncthreads();
    float m2 = fmaxf(fmaxf(s_r3[0], s_r3[1]), fmaxf(s_r3[2], s_r3[3]));
    if (tid < 128) {
        float e = expf(2.0f * lw - m2);
#pragma unroll
        for (int off = 16; off; off >>= 1) e += __shfl_xor_sync(0xffffffffu, e, off);
        if (lane == 0) s_r4[w] = e;
    }
    __syncthreads();
    if (tid == 0) {
        float log_ess = -(logf(s_r4[0] + s_r4[1] + s_r4[2] + s_r4[3]) + m2);
        s_flag = (expf(log_ess) < 64.0f) ? 1.0f : 0.0f;
        float lpn = g_lp[b] + lse;
        g_lp[b] = lpn;
        if (t == T_ - 1) out[b] = lpn;
    }
    __syncthreads();
    bool need = (s_flag != 0.0f);

    if (need) {
        const unsigned kr0 = g_keys[t * 4 + 2], kr1 = g_keys[t * 4 + 3];
        for (int i = 0; i < 16; ++i) {
            int p = w * 16 + i;
            unsigned base = ((unsigned)p * B_ + (unsigned)b) * P_;
            float bv = -3.4e38f;
            int bj = 0;
#pragma unroll
            for (int jj = 0; jj < 4; ++jj) {
                int j = lane * 4 + jj;
                float v = gumbel_draw(kr0, kr1, base + (unsigned)j) + s_lw[j];
                if (v > bv) { bv = v; bj = j; }
            }
#pragma unroll
            for (int off = 16; off; off >>= 1) {
                float ov = __shfl_xor_sync(0xffffffffu, bv, off);
                int   oj = __shfl_xor_sync(0xffffffffu, bj, off);
                if (ov > bv || (ov == bv && oj < bj)) { bv = ov; bj = oj; }
            }
            if (lane < 16) {
                const float4* src = (const float4*)&g_znew[(b * P_ + bj) * L_];
                float4* dst = (float4*)&g_z[(b * P_ + p) * L_];
                dst[lane] = src[lane];
            }
            if (lane == 0) g_lw[b * P_ + p] = -LOGP_;
        }
    } else {
        if (tid < 128) g_lw[b * P_ + tid] = lw;   // g_z already holds z_new
    }

    // ---- gi_xy for step t+1 ----
    if (t + 1 < T_) {
#pragma unroll
        for (int m = 0; m < 3; ++m) {
            int j = tid + m * 256;
            float acc = b_ih[j];
            for (int k = 0; k < 64; ++k)
                acc = fmaf(g_Wxy[k * 768 + j], s_emb[k], acc);
            acc = fmaf(g_Wxy[64 * 768 + j], s_emb[64], acc);
            acc = fmaf(g_Wxy[65 * 768 + j], s_emb[65], acc);
            g_gixy[b * 768 + j] = acc;
        }
    }
}

// ---------------- launch ----------------
extern "C" void kernel_launch(void* const* d_in, const int* in_sizes, int n_in,
                              void* d_out, int out_size) {
    const float* x     = (const float*)d_in[0];
    const float* y     = (const float*)d_in[1];
    const float* W_emb = (const float*)d_in[2];
    const float* b_emb = (const float*)d_in[3];
    const float* W_ih  = (const float*)d_in[4];
    const float* W_hh  = (const float*)d_in[5];
    const float* b_ih  = (const float*)d_in[6];
    const float* b_hh  = (const float*)d_in[7];
    const float* W_enc = (const float*)d_in[8];
    const float* b_enc = (const float*)d_in[9];
    const float* W_pr  = (const float*)d_in[10];
    const float* b_pr  = (const float*)d_in[11];
    const float* W_dec = (const float*)d_in[12];
    const float* b_dec = (const float*)d_in[13];
    float* out = (float*)d_out;

    k_setup<<<1024, 256>>>(x, y, W_emb, b_emb, W_ih, W_hh, W_enc, W_pr, b_ih);
    for (int t = 0; t < T_; ++t) {
        k_particle<<<BP_ / 16, 256>>>(y, b_hh, b_enc, b_pr, W_dec, b_dec, t);
        k_batch<<<B_, 256>>>(out, y, b_ih, t);
    }
}